// round 14
// baseline (speedup 1.0000x reference)
#include <cuda_runtime.h>

// UnPooling (max-unpool 2x2): x [16,128,128,256] f32, pooled [16,64,64,256] f32
// out [16,128,128,256] f32: max(pooled,0) at argmax slot of each 2x2 window, else 0.
//
// NHWC, hardcoded: N=16, H=128, W=128, C=256, Hp=64, Wp=64.
// FINAL — converged at the HBM roofline (10 identical-config runs:
// kernel 82.2-83.8us, 6.58-6.70 TB/s, DRAM busy 83-85%, rel_err 0).
// 604 MB irreducible traffic / achievable R+W-mix bandwidth == measured time;
// issue 13%, alu 18% -> DRAM is the sole binding resource; residual DRAM idle
// is read/write bus turnaround, unreachable from the SM side.
// Ruled out by measurement: streaming/L2 hints (neutral), 256-bit accesses
// (occupancy loss, -3%), persistent grid (MLP/page-locality loss, -7%),
// block-size changes (neutral). Ruled out analytically: sparse scatter
// (write-allocate RMW), TMA (LTS cap path-independent), CTA swizzle
// (addr->die hash ~Bernoulli @2KB grain).
// CV = C/4 = 64 float4 per pixel; x row stride 8192, col stride 64 (float4 units).

__global__ __launch_bounds__(512) void unpool_kernel(const float4* __restrict__ x,
                                                     const float4* __restrict__ pooled,
                                                     float4* __restrict__ out,
                                                     int total)
{
    int tid = blockIdx.x * blockDim.x + threadIdx.x;
    if (tid >= total) return;

    // tid linear over pooled in float4 units: ((n*Hp+hp)*Wp+wp)*CV + cv
    int cv = tid & 63;          // CV = 64
    int wp = (tid >> 6) & 63;   // Wp = 64
    int hp = (tid >> 12) & 63;  // Hp = 64
    int n  = tid >> 18;

    // base float4 index into x/out at (n, 2*hp, 2*wp, cv)
    int b = ((n * 128 + 2 * hp) * 128 + 2 * wp) * 64 + cv;

    float4 v00 = x[b];
    float4 v01 = x[b + 64];      // (dh=0, dw=1)
    float4 v10 = x[b + 8192];    // (dh=1, dw=0)
    float4 v11 = x[b + 8256];    // (dh=1, dw=1)
    float4 p   = pooled[tid];

    float4 o00, o01, o10, o11;

    // Row-major (dh,dw) order, first-max tie-break => strict '>' for later slots.
#define UNPOOL_COMP(F)                                                \
    {                                                                 \
        float t0 = v00.F, t1 = v01.F, t2 = v10.F, t3 = v11.F;         \
        int   idx = 0;                                                \
        float best = t0;                                              \
        if (t1 > best) { best = t1; idx = 1; }                        \
        if (t2 > best) { best = t2; idx = 2; }                        \
        if (t3 > best) { best = t3; idx = 3; }                        \
        float pv = fmaxf(p.F, 0.0f);                                  \
        o00.F = (idx == 0) ? pv : 0.0f;                               \
        o01.F = (idx == 1) ? pv : 0.0f;                               \
        o10.F = (idx == 2) ? pv : 0.0f;                               \
        o11.F = (idx == 3) ? pv : 0.0f;                               \
    }

    UNPOOL_COMP(x)
    UNPOOL_COMP(y)
    UNPOOL_COMP(z)
    UNPOOL_COMP(w)
#undef UNPOOL_COMP

    out[b]        = o00;
    out[b + 64]   = o01;
    out[b + 8192] = o10;
    out[b + 8256] = o11;
}

extern "C" void kernel_launch(void* const* d_in, const int* in_sizes, int n_in,
                              void* d_out, int out_size)
{
    const float4* x      = (const float4*)d_in[0];
    const float4* pooled = (const float4*)d_in[1];
    float4*       out    = (float4*)d_out;

    const int total = 16 * 64 * 64 * 64;   // pooled float4 count = 4,194,304
    const int threads = 512;
    const int blocks  = (total + threads - 1) / threads;
    unpool_kernel<<<blocks, threads>>>(x, pooled, out, total);
}

// round 15
// speedup vs baseline: 1.0032x; 1.0032x over previous
#include <cuda_runtime.h>

// UnPooling (max-unpool 2x2): x [16,128,128,256] f32, pooled [16,64,64,256] f32
// out [16,128,128,256] f32: max(pooled,0) at argmax slot of each 2x2 window, else 0.
//
// NHWC, hardcoded: N=16, H=128, W=128, C=256, Hp=64, Wp=64.
// FINAL — converged at the HBM roofline (11 identical-config runs:
// kernel 82.2-83.8us, 6.58-6.70 TB/s, DRAM busy 83-85%, rel_err 0).
// 604 MB irreducible traffic / achievable R+W-mix bandwidth == measured time;
// issue 13%, alu 18% -> DRAM is the sole binding resource; residual DRAM idle
// is read/write bus turnaround, unreachable from the SM side.
// Ruled out by measurement: streaming/L2 hints (neutral), 256-bit accesses
// (occupancy loss, -3%), persistent grid (MLP/page-locality loss, -7%),
// block-size changes (neutral). Ruled out analytically: sparse scatter
// (write-allocate RMW), TMA (LTS cap path-independent), CTA swizzle
// (addr->die hash ~Bernoulli @2KB grain).
// CV = C/4 = 64 float4 per pixel; x row stride 8192, col stride 64 (float4 units).

__global__ __launch_bounds__(512) void unpool_kernel(const float4* __restrict__ x,
                                                     const float4* __restrict__ pooled,
                                                     float4* __restrict__ out,
                                                     int total)
{
    int tid = blockIdx.x * blockDim.x + threadIdx.x;
    if (tid >= total) return;

    // tid linear over pooled in float4 units: ((n*Hp+hp)*Wp+wp)*CV + cv
    int cv = tid & 63;          // CV = 64
    int wp = (tid >> 6) & 63;   // Wp = 64
    int hp = (tid >> 12) & 63;  // Hp = 64
    int n  = tid >> 18;

    // base float4 index into x/out at (n, 2*hp, 2*wp, cv)
    int b = ((n * 128 + 2 * hp) * 128 + 2 * wp) * 64 + cv;

    float4 v00 = x[b];
    float4 v01 = x[b + 64];      // (dh=0, dw=1)
    float4 v10 = x[b + 8192];    // (dh=1, dw=0)
    float4 v11 = x[b + 8256];    // (dh=1, dw=1)
    float4 p   = pooled[tid];

    float4 o00, o01, o10, o11;

    // Row-major (dh,dw) order, first-max tie-break => strict '>' for later slots.
#define UNPOOL_COMP(F)                                                \
    {                                                                 \
        float t0 = v00.F, t1 = v01.F, t2 = v10.F, t3 = v11.F;         \
        int   idx = 0;                                                \
        float best = t0;                                              \
        if (t1 > best) { best = t1; idx = 1; }                        \
        if (t2 > best) { best = t2; idx = 2; }                        \
        if (t3 > best) { best = t3; idx = 3; }                        \
        float pv = fmaxf(p.F, 0.0f);                                  \
        o00.F = (idx == 0) ? pv : 0.0f;                               \
        o01.F = (idx == 1) ? pv : 0.0f;                               \
        o10.F = (idx == 2) ? pv : 0.0f;                               \
        o11.F = (idx == 3) ? pv : 0.0f;                               \
    }

    UNPOOL_COMP(x)
    UNPOOL_COMP(y)
    UNPOOL_COMP(z)
    UNPOOL_COMP(w)
#undef UNPOOL_COMP

    out[b]        = o00;
    out[b + 64]   = o01;
    out[b + 8192] = o10;
    out[b + 8256] = o11;
}

extern "C" void kernel_launch(void* const* d_in, const int* in_sizes, int n_in,
                              void* d_out, int out_size)
{
    const float4* x      = (const float4*)d_in[0];
    const float4* pooled = (const float4*)d_in[1];
    float4*       out    = (float4*)d_out;

    const int total = 16 * 64 * 64 * 64;   // pooled float4 count = 4,194,304
    const int threads = 512;
    const int blocks  = (total + threads - 1) / threads;
    unpool_kernel<<<blocks, threads>>>(x, pooled, out, total);
}

// round 16
// speedup vs baseline: 1.0113x; 1.0081x over previous
#include <cuda_runtime.h>

// UnPooling (max-unpool 2x2): x [16,128,128,256] f32, pooled [16,64,64,256] f32
// out [16,128,128,256] f32: max(pooled,0) at argmax slot of each 2x2 window, else 0.
//
// NHWC, hardcoded: N=16, H=128, W=128, C=256, Hp=64, Wp=64.
// FINAL — converged at the HBM roofline (12 identical-config runs:
// kernel 82.2-83.8us, 6.58-6.70 TB/s, DRAM busy 83-85%, rel_err 0).
// 604 MB irreducible traffic / achievable R+W-mix bandwidth == measured time;
// issue 13%, alu 18% -> DRAM is the sole binding resource; residual DRAM idle
// is read/write bus turnaround, unreachable from the SM side.
// Ruled out by measurement: streaming/L2 hints (neutral), 256-bit accesses
// (occupancy loss, -3%), persistent grid (MLP/page-locality loss, -7%),
// block-size changes (neutral). Ruled out analytically: sparse scatter
// (write-allocate RMW), TMA (LTS cap path-independent), CTA swizzle
// (addr->die hash ~Bernoulli @2KB grain).
// CV = C/4 = 64 float4 per pixel; x row stride 8192, col stride 64 (float4 units).

__global__ __launch_bounds__(512) void unpool_kernel(const float4* __restrict__ x,
                                                     const float4* __restrict__ pooled,
                                                     float4* __restrict__ out,
                                                     int total)
{
    int tid = blockIdx.x * blockDim.x + threadIdx.x;
    if (tid >= total) return;

    // tid linear over pooled in float4 units: ((n*Hp+hp)*Wp+wp)*CV + cv
    int cv = tid & 63;          // CV = 64
    int wp = (tid >> 6) & 63;   // Wp = 64
    int hp = (tid >> 12) & 63;  // Hp = 64
    int n  = tid >> 18;

    // base float4 index into x/out at (n, 2*hp, 2*wp, cv)
    int b = ((n * 128 + 2 * hp) * 128 + 2 * wp) * 64 + cv;

    float4 v00 = x[b];
    float4 v01 = x[b + 64];      // (dh=0, dw=1)
    float4 v10 = x[b + 8192];    // (dh=1, dw=0)
    float4 v11 = x[b + 8256];    // (dh=1, dw=1)
    float4 p   = pooled[tid];

    float4 o00, o01, o10, o11;

    // Row-major (dh,dw) order, first-max tie-break => strict '>' for later slots.
#define UNPOOL_COMP(F)                                                \
    {                                                                 \
        float t0 = v00.F, t1 = v01.F, t2 = v10.F, t3 = v11.F;         \
        int   idx = 0;                                                \
        float best = t0;                                              \
        if (t1 > best) { best = t1; idx = 1; }                        \
        if (t2 > best) { best = t2; idx = 2; }                        \
        if (t3 > best) { best = t3; idx = 3; }                        \
        float pv = fmaxf(p.F, 0.0f);                                  \
        o00.F = (idx == 0) ? pv : 0.0f;                               \
        o01.F = (idx == 1) ? pv : 0.0f;                               \
        o10.F = (idx == 2) ? pv : 0.0f;                               \
        o11.F = (idx == 3) ? pv : 0.0f;                               \
    }

    UNPOOL_COMP(x)
    UNPOOL_COMP(y)
    UNPOOL_COMP(z)
    UNPOOL_COMP(w)
#undef UNPOOL_COMP

    out[b]        = o00;
    out[b + 64]   = o01;
    out[b + 8192] = o10;
    out[b + 8256] = o11;
}

extern "C" void kernel_launch(void* const* d_in, const int* in_sizes, int n_in,
                              void* d_out, int out_size)
{
    const float4* x      = (const float4*)d_in[0];
    const float4* pooled = (const float4*)d_in[1];
    float4*       out    = (float4*)d_out;

    const int total = 16 * 64 * 64 * 64;   // pooled float4 count = 4,194,304
    const int threads = 512;
    const int blocks  = (total + threads - 1) / threads;
    unpool_kernel<<<blocks, threads>>>(x, pooled, out, total);
}